// round 16
// baseline (speedup 1.0000x reference)
#include <cuda_runtime.h>
#include <cuda_fp16.h>
#include <cstdint>

// Problem dims (fixed by the reference)
#define MDIM 4096
#define KDIM 4096
#define NDIM 11008

// GEMM tiling (R15 config: best measured passing kernel)
#define BM 128
#define BN 128
#define BK 64
#define NKITERS (KDIM / BK)   // 64

// Scratch (device globals -- no runtime allocation allowed)
__device__ __half g_Xh[(size_t)MDIM * KDIM];
__device__ __half g_Wh[(size_t)NDIM * KDIM];
__device__ float  g_rowsum[MDIM];

// ---------------------------------------------------------------------------
// Helpers
// ---------------------------------------------------------------------------
__device__ __forceinline__ uint32_t smem_to_u32(const void* p) {
    uint32_t a;
    asm("{ .reg .u64 t; cvta.to.shared.u64 t, %1; cvt.u32.u64 %0, t; }"
        : "=r"(a) : "l"(p));
    return a;
}

#define CP_ASYNC_16(dst, src) \
    asm volatile("cp.async.cg.shared.global [%0], [%1], 16;" \
        :: "r"(dst), "l"(src) : "memory")
#define CP_ASYNC_COMMIT() asm volatile("cp.async.commit_group;" ::: "memory")
#define CP_ASYNC_WAIT(n)  asm volatile("cp.async.wait_group %0;" :: "n"(n) : "memory")

__device__ __forceinline__ void ldsm_x4(uint32_t& r0, uint32_t& r1,
                                        uint32_t& r2, uint32_t& r3, uint32_t addr) {
    asm volatile("ldmatrix.sync.aligned.m8n8.x4.shared.b16 {%0,%1,%2,%3}, [%4];"
        : "=r"(r0), "=r"(r1), "=r"(r2), "=r"(r3) : "r"(addr));
}

__device__ __forceinline__ void mma16816(float* c, const uint32_t* a,
                                         const uint32_t* b) {
    asm volatile(
        "mma.sync.aligned.m16n8k16.row.col.f32.f16.f16.f32 "
        "{%0,%1,%2,%3}, {%4,%5,%6,%7}, {%8,%9}, {%0,%1,%2,%3};"
        : "+f"(c[0]), "+f"(c[1]), "+f"(c[2]), "+f"(c[3])
        : "r"(a[0]), "r"(a[1]), "r"(a[2]), "r"(a[3]), "r"(b[0]), "r"(b[1]));
}

// ---------------------------------------------------------------------------
// Merged prep (proven): blocks [0, MDIM) convert x rows (+ rowsum);
//                       blocks [MDIM, ...) convert weight int32 -> fp16.
// Weight reads use __ldcs (streamed once; keep L2 for useful data).
// ---------------------------------------------------------------------------
#define WCHUNKS ((((size_t)NDIM * KDIM) / 4 + 255) / 256)   // int4 chunks of 256 thr

__global__ void prep_kernel(const float* __restrict__ x, const int* __restrict__ w) {
    const int tid = threadIdx.x;
    if (blockIdx.x < MDIM) {
        const int m = blockIdx.x;
        const float4* xr = reinterpret_cast<const float4*>(x + (size_t)m * KDIM);
        uint2* outr = reinterpret_cast<uint2*>(g_Xh + (size_t)m * KDIM);
        float sum = 0.f;
        #pragma unroll 4
        for (int i = tid; i < KDIM / 4; i += 256) {
            float4 v = xr[i];
            sum += (v.x + v.y) + (v.z + v.w);
            __half2 h0 = __floats2half2_rn(v.x, v.y);
            __half2 h1 = __floats2half2_rn(v.z, v.w);
            uint2 u;
            u.x = *reinterpret_cast<const unsigned*>(&h0);
            u.y = *reinterpret_cast<const unsigned*>(&h1);
            outr[i] = u;
        }
        __shared__ float red[8];
        #pragma unroll
        for (int o = 16; o; o >>= 1) sum += __shfl_xor_sync(0xFFFFFFFFu, sum, o);
        if ((tid & 31) == 0) red[tid >> 5] = sum;
        __syncthreads();
        if (tid == 0) {
            float s = 0.f;
            #pragma unroll
            for (int i = 0; i < 8; i++) s += red[i];
            g_rowsum[m] = s;
        }
    } else {
        size_t idx = (size_t)(blockIdx.x - MDIM) * 256 + tid;   // int4 index
        if (idx >= ((size_t)NDIM * KDIM) / 4) return;
        int4 v = __ldcs(reinterpret_cast<const int4*>(w) + idx);
        __half2 h0 = __halves2half2(__int2half_rn(v.x), __int2half_rn(v.y));
        __half2 h1 = __halves2half2(__int2half_rn(v.z), __int2half_rn(v.w));
        uint2 u;
        u.x = *reinterpret_cast<const unsigned*>(&h0);
        u.y = *reinterpret_cast<const unsigned*>(&h1);
        reinterpret_cast<uint2*>(g_Wh)[idx] = u;
    }
}

// ---------------------------------------------------------------------------
// GEMM: R15 frame (128x128x64, 8 warps 2x4 @ 64x32, 2-stage cp.async,
// 2 CTAs/SM, raster x=M / y=N, ONE __syncthreads per k-iter) with the
// next-stage cp.asyncs SPREAD across the 4 ks slices (R6-proven ordering:
// single COMMIT after the mma block). First ldmatrix now issues immediately
// after the barrier instead of behind an 8-deep cp.async burst.
//   WAIT(0); __syncthreads();
//   for ks: { 2 cp.async for kc+1 ; ldsm(ks) ; mma(ks) }
//   COMMIT;
// SMEM: buf0 A@0 (16KB) B@16384 | buf1 A@32768 B@49152 (64KB -> 2 CTAs/SM).
// Swizzle for 128B rows: addr = row*128 + (col ^ ((row&7)*16)).
// ---------------------------------------------------------------------------
#define SMEM_BYTES 65536

// one quarter of a stage's loads: 1 A row + 1 B row per thread (256 threads)
__device__ __forceinline__ void load_chunk(uint32_t sA, uint32_t sB,
                                           const uint4* __restrict__ gA,
                                           const uint4* __restrict__ gB,
                                           int kc, int m0, int n0,
                                           int tid, int it) {
    const int r0 = tid >> 3;            // 0..31
    const int c16 = tid & 7;            // 16B column index 0..7
    const uint32_t swz = (uint32_t)((c16 ^ (r0 & 7)) * 16);
    const int row = r0 + it * 32;
    CP_ASYNC_16(sA + (uint32_t)row * 128 + swz,
                gA + (size_t)(m0 + row) * (KDIM / 8) + kc * 8 + c16);
    CP_ASYNC_16(sB + (uint32_t)row * 128 + swz,
                gB + (size_t)(n0 + row) * (KDIM / 8) + kc * 8 + c16);
}

__global__ void __launch_bounds__(256, 2) gemm_kernel(
    const float* __restrict__ scale, const float* __restrict__ offs,
    const float* __restrict__ bias, float* __restrict__ out)
{
    extern __shared__ char smem[];
    const int tid = threadIdx.x;
    const int wid = tid >> 5;
    const int lane = tid & 31;
    const uint32_t sbase = smem_to_u32(smem);

    // raster: x = M-tile, y = N-tile (A L2-resident, B streams once)
    const int m0 = blockIdx.x * BM;
    const int n0 = blockIdx.y * BN;

    // warp layout: 2 (m) x 4 (n); warp tile 64m x 32n
    const int wm = (wid >> 2) * 64;
    const int wn = (wid & 3) * 32;

    const uint4* gA = reinterpret_cast<const uint4*>(g_Xh);
    const uint4* gB = reinterpret_cast<const uint4*>(g_Wh);

    float acc[4][4][4];
    #pragma unroll
    for (int i = 0; i < 4; ++i)
        #pragma unroll
        for (int j = 0; j < 4; ++j)
            #pragma unroll
            for (int k = 0; k < 4; ++k) acc[i][j][k] = 0.f;

    // Precomputed ldmatrix address components
    const int aRow = (lane & 15);
    const uint32_t aColB = (uint32_t)((lane >> 4) * 16);
    const int bRow = (lane & 7) + ((lane >> 4) * 8);
    const uint32_t bColB = (uint32_t)(((lane >> 3) & 1) * 16);

    // prologue: stage 0 (all 8 cp.asyncs, then commit)
    #pragma unroll
    for (int it = 0; it < 4; ++it)
        load_chunk(sbase, sbase + 16384u, gA, gB, 0, m0, n0, tid, it);
    CP_ASYNC_COMMIT();

    for (int kc = 0; kc < NKITERS; ++kc) {
        // only the group for stage kc is pending; drain it fully
        CP_ASYNC_WAIT(0);
        __syncthreads();   // kc visible; everyone done reading buf (kc+1)&1

        const uint32_t bufo = (uint32_t)(kc & 1) * 32768u;
        const uint32_t sA = sbase + bufo;
        const uint32_t sB = sbase + bufo + 16384u;
        const uint32_t nbufo = (uint32_t)((kc + 1) & 1) * 32768u;
        const uint32_t nA = sbase + nbufo;
        const uint32_t nB = sbase + nbufo + 16384u;
        const bool do_load = (kc + 1 < NKITERS);

        #pragma unroll
        for (int ks = 0; ks < 4; ++ks) {
            // spread: one quarter of next stage's loads per slice
            if (do_load)
                load_chunk(nA, nB, gA, gB, kc + 1, m0, n0, tid, ks);

            uint32_t a[4][4], b[4][2];
            #pragma unroll
            for (int mi = 0; mi < 4; ++mi) {
                int row = wm + mi * 16 + aRow;
                uint32_t col = (aColB + (uint32_t)ks * 32) ^ (uint32_t)((row & 7) * 16);
                ldsm_x4(a[mi][0], a[mi][1], a[mi][2], a[mi][3],
                        sA + (uint32_t)row * 128 + col);
            }
            #pragma unroll
            for (int np = 0; np < 2; ++np) {
                int row = wn + np * 16 + bRow;
                uint32_t col = (bColB + (uint32_t)ks * 32) ^ (uint32_t)((row & 7) * 16);
                ldsm_x4(b[np * 2][0], b[np * 2][1], b[np * 2 + 1][0], b[np * 2 + 1][1],
                        sB + (uint32_t)row * 128 + col);
            }
            #pragma unroll
            for (int mi = 0; mi < 4; ++mi)
                #pragma unroll
                for (int ni = 0; ni < 4; ++ni)
                    mma16816(acc[mi][ni], a[mi], b[ni]);
        }
        CP_ASYNC_COMMIT();   // single group for stage kc+1 (uniform accounting)
    }

    // ---------------- fused dequant epilogue (regs -> gmem) ----------------
    // Output stores use __stcs: 'out' is never re-read; keep L2 for A/B.
    const int g = lane >> 2;
    const int tg = lane & 3;
    #pragma unroll
    for (int mi = 0; mi < 4; ++mi) {
        const int mrow0 = m0 + wm + mi * 16 + g;
        const float rs0 = g_rowsum[mrow0];
        const float rs1 = g_rowsum[mrow0 + 8];
        float* o0 = out + (size_t)mrow0 * NDIM + n0 + wn;
        float* o1 = o0 + (size_t)8 * NDIM;
        #pragma unroll
        for (int ni = 0; ni < 4; ++ni) {
            const int n = n0 + wn + ni * 8 + tg * 2;
            const float2 sc = *reinterpret_cast<const float2*>(scale + n);
            const float2 of = *reinterpret_cast<const float2*>(offs + n);
            const float2 bi = *reinterpret_cast<const float2*>(bias + n);
            const float sox = sc.x * of.x, soy = sc.y * of.y;
            float2 r0v, r1v;
            r0v.x = fmaf(acc[mi][ni][0], sc.x, fmaf(sox, rs0, bi.x));
            r0v.y = fmaf(acc[mi][ni][1], sc.y, fmaf(soy, rs0, bi.y));
            r1v.x = fmaf(acc[mi][ni][2], sc.x, fmaf(sox, rs1, bi.x));
            r1v.y = fmaf(acc[mi][ni][3], sc.y, fmaf(soy, rs1, bi.y));
            __stcs(reinterpret_cast<float2*>(o0 + ni * 8 + tg * 2), r0v);
            __stcs(reinterpret_cast<float2*>(o1 + ni * 8 + tg * 2), r1v);
        }
    }
}

// ---------------------------------------------------------------------------
// Launch
// ---------------------------------------------------------------------------
extern "C" void kernel_launch(void* const* d_in, const int* in_sizes, int n_in,
                              void* d_out, int out_size) {
    const float* x    = (const float*)d_in[0];
    const int*   w    = (const int*)  d_in[1];
    const float* scal = (const float*)d_in[2];
    const float* offs = (const float*)d_in[3];
    const float* bias = (const float*)d_in[4];
    float* out = (float*)d_out;

    cudaFuncSetAttribute(gemm_kernel,
                         cudaFuncAttributeMaxDynamicSharedMemorySize, SMEM_BYTES);

    const unsigned prep_blocks = (unsigned)(MDIM + WCHUNKS);
    prep_kernel<<<prep_blocks, 256>>>(x, w);
    gemm_kernel<<<dim3(MDIM / BM, NDIM / BN), 256, SMEM_BYTES>>>(scal, offs, bias, out);
}

// round 17
// speedup vs baseline: 1.0285x; 1.0285x over previous
#include <cuda_runtime.h>
#include <cuda_fp16.h>
#include <cstdint>

// Problem dims (fixed by the reference)
#define MDIM 4096
#define KDIM 4096
#define NDIM 11008

// GEMM tiling (R15 config: best measured passing kernel, 842.1 us)
#define BM 128
#define BN 128
#define BK 64
#define NKITERS (KDIM / BK)   // 64

// Scratch (device globals -- no runtime allocation allowed)
__device__ __half g_Xh[(size_t)MDIM * KDIM];
__device__ __half g_Wh[(size_t)NDIM * KDIM];
__device__ float  g_rowsum[MDIM];

// ---------------------------------------------------------------------------
// Helpers
// ---------------------------------------------------------------------------
__device__ __forceinline__ uint32_t smem_to_u32(const void* p) {
    uint32_t a;
    asm("{ .reg .u64 t; cvta.to.shared.u64 t, %1; cvt.u32.u64 %0, t; }"
        : "=r"(a) : "l"(p));
    return a;
}

#define CP_ASYNC_16(dst, src) \
    asm volatile("cp.async.cg.shared.global [%0], [%1], 16;" \
        :: "r"(dst), "l"(src) : "memory")
#define CP_ASYNC_COMMIT() asm volatile("cp.async.commit_group;" ::: "memory")
#define CP_ASYNC_WAIT(n)  asm volatile("cp.async.wait_group %0;" :: "n"(n) : "memory")

__device__ __forceinline__ void ldsm_x4(uint32_t& r0, uint32_t& r1,
                                        uint32_t& r2, uint32_t& r3, uint32_t addr) {
    asm volatile("ldmatrix.sync.aligned.m8n8.x4.shared.b16 {%0,%1,%2,%3}, [%4];"
        : "=r"(r0), "=r"(r1), "=r"(r2), "=r"(r3) : "r"(addr));
}

__device__ __forceinline__ void mma16816(float* c, const uint32_t* a,
                                         const uint32_t* b) {
    asm volatile(
        "mma.sync.aligned.m16n8k16.row.col.f32.f16.f16.f32 "
        "{%0,%1,%2,%3}, {%4,%5,%6,%7}, {%8,%9}, {%0,%1,%2,%3};"
        : "+f"(c[0]), "+f"(c[1]), "+f"(c[2]), "+f"(c[3])
        : "r"(a[0]), "r"(a[1]), "r"(a[2]), "r"(a[3]), "r"(b[0]), "r"(b[1]));
}

// ---------------------------------------------------------------------------
// Merged prep (proven): blocks [0, MDIM) convert x rows (+ rowsum);
//                       blocks [MDIM, ...) convert weight int32 -> fp16.
// ---------------------------------------------------------------------------
#define WCHUNKS ((((size_t)NDIM * KDIM) / 4 + 255) / 256)   // int4 chunks of 256 thr

__global__ void prep_kernel(const float* __restrict__ x, const int* __restrict__ w) {
    const int tid = threadIdx.x;
    if (blockIdx.x < MDIM) {
        const int m = blockIdx.x;
        const float4* xr = reinterpret_cast<const float4*>(x + (size_t)m * KDIM);
        uint2* outr = reinterpret_cast<uint2*>(g_Xh + (size_t)m * KDIM);
        float sum = 0.f;
        #pragma unroll 4
        for (int i = tid; i < KDIM / 4; i += 256) {
            float4 v = xr[i];
            sum += (v.x + v.y) + (v.z + v.w);
            __half2 h0 = __floats2half2_rn(v.x, v.y);
            __half2 h1 = __floats2half2_rn(v.z, v.w);
            uint2 u;
            u.x = *reinterpret_cast<const unsigned*>(&h0);
            u.y = *reinterpret_cast<const unsigned*>(&h1);
            outr[i] = u;
        }
        __shared__ float red[8];
        #pragma unroll
        for (int o = 16; o; o >>= 1) sum += __shfl_xor_sync(0xFFFFFFFFu, sum, o);
        if ((tid & 31) == 0) red[tid >> 5] = sum;
        __syncthreads();
        if (tid == 0) {
            float s = 0.f;
            #pragma unroll
            for (int i = 0; i < 8; i++) s += red[i];
            g_rowsum[m] = s;
        }
    } else {
        size_t idx = (size_t)(blockIdx.x - MDIM) * 256 + tid;   // int4 index
        if (idx >= ((size_t)NDIM * KDIM) / 4) return;
        int4 v = reinterpret_cast<const int4*>(w)[idx];
        __half2 h0 = __halves2half2(__int2half_rn(v.x), __int2half_rn(v.y));
        __half2 h1 = __halves2half2(__int2half_rn(v.z), __int2half_rn(v.w));
        uint2 u;
        u.x = *reinterpret_cast<const unsigned*>(&h0);
        u.y = *reinterpret_cast<const unsigned*>(&h1);
        reinterpret_cast<uint2*>(g_Wh)[idx] = u;
    }
}

// ---------------------------------------------------------------------------
// GEMM (byte-exact R15, the session best): 128x128x64 tile, 8 warps (2x4,
// warp 64x32), 2-stage cp.async, 2 CTAs/SM, raster x=M / y=N (A L2-resident,
// B streams once), ONE __syncthreads per k-iter:
//   WAIT(0)            -- only group kc pending; full drain
//   __syncthreads()    -- kc's data visible; all warps done with buf (kc+1)&1
//   load_tiles(kc+1)   -- full 8-deep burst into the freed buffer
//   COMMIT; mma(buf kc&1)
// SMEM: buf0 A@0 (16KB) B@16384 | buf1 A@32768 B@49152 (64KB -> 2 CTAs/SM).
// Swizzle for 128B rows: addr = row*128 + (col ^ ((row&7)*16)).
// ---------------------------------------------------------------------------
#define SMEM_BYTES 65536

__device__ __forceinline__ void load_tiles(uint32_t sA, uint32_t sB,
                                           const uint4* __restrict__ gA,
                                           const uint4* __restrict__ gB,
                                           int kc, int m0, int n0, int tid) {
    const int r0 = tid >> 3;            // 0..31
    const int c16 = tid & 7;            // 16B column index 0..7
    const uint32_t swz = (uint32_t)((c16 ^ (r0 & 7)) * 16);
    #pragma unroll
    for (int it = 0; it < 4; ++it) {
        int row = r0 + it * 32;
        uint32_t dst = sA + (uint32_t)row * 128 + swz;
        const uint4* src = gA + (size_t)(m0 + row) * (KDIM / 8) + kc * 8 + c16;
        CP_ASYNC_16(dst, src);
    }
    #pragma unroll
    for (int it = 0; it < 4; ++it) {
        int row = r0 + it * 32;
        uint32_t dst = sB + (uint32_t)row * 128 + swz;
        const uint4* src = gB + (size_t)(n0 + row) * (KDIM / 8) + kc * 8 + c16;
        CP_ASYNC_16(dst, src);
    }
}

__global__ void __launch_bounds__(256, 2) gemm_kernel(
    const float* __restrict__ scale, const float* __restrict__ offs,
    const float* __restrict__ bias, float* __restrict__ out)
{
    extern __shared__ char smem[];
    const int tid = threadIdx.x;
    const int wid = tid >> 5;
    const int lane = tid & 31;
    const uint32_t sbase = smem_to_u32(smem);

    // raster: x = M-tile, y = N-tile (A L2-resident, B streams once)
    const int m0 = blockIdx.x * BM;
    const int n0 = blockIdx.y * BN;

    // warp layout: 2 (m) x 4 (n); warp tile 64m x 32n
    const int wm = (wid >> 2) * 64;
    const int wn = (wid & 3) * 32;

    const uint4* gA = reinterpret_cast<const uint4*>(g_Xh);
    const uint4* gB = reinterpret_cast<const uint4*>(g_Wh);

    float acc[4][4][4];
    #pragma unroll
    for (int i = 0; i < 4; ++i)
        #pragma unroll
        for (int j = 0; j < 4; ++j)
            #pragma unroll
            for (int k = 0; k < 4; ++k) acc[i][j][k] = 0.f;

    // Precomputed ldmatrix address components
    const int aRow = (lane & 15);
    const uint32_t aColB = (uint32_t)((lane >> 4) * 16);
    const int bRow = (lane & 7) + ((lane >> 4) * 8);
    const uint32_t bColB = (uint32_t)(((lane >> 3) & 1) * 16);

    // prologue: stage 0
    load_tiles(sbase, sbase + 16384, gA, gB, 0, m0, n0, tid);
    CP_ASYNC_COMMIT();

    for (int kc = 0; kc < NKITERS; ++kc) {
        // only the group for stage kc is pending; drain it fully
        CP_ASYNC_WAIT(0);
        __syncthreads();   // kc visible; everyone done reading buf (kc+1)&1

        // issue loads for kc+1 into the buffer just proven free; they land
        // while the mma block below runs
        if (kc + 1 < NKITERS) {
            const uint32_t nbufo = (uint32_t)((kc + 1) & 1) * 32768u;
            load_tiles(sbase + nbufo, sbase + nbufo + 16384, gA, gB,
                       kc + 1, m0, n0, tid);
        }
        CP_ASYNC_COMMIT();   // uniform group accounting every iteration

        const uint32_t bufo = (uint32_t)(kc & 1) * 32768u;
        const uint32_t sA = sbase + bufo;
        const uint32_t sB = sbase + bufo + 16384;

        #pragma unroll
        for (int ks = 0; ks < 4; ++ks) {
            uint32_t a[4][4], b[4][2];
            #pragma unroll
            for (int mi = 0; mi < 4; ++mi) {
                int row = wm + mi * 16 + aRow;
                uint32_t col = (aColB + (uint32_t)ks * 32) ^ (uint32_t)((row & 7) * 16);
                ldsm_x4(a[mi][0], a[mi][1], a[mi][2], a[mi][3],
                        sA + (uint32_t)row * 128 + col);
            }
            #pragma unroll
            for (int np = 0; np < 2; ++np) {
                int row = wn + np * 16 + bRow;
                uint32_t col = (bColB + (uint32_t)ks * 32) ^ (uint32_t)((row & 7) * 16);
                ldsm_x4(b[np * 2][0], b[np * 2][1], b[np * 2 + 1][0], b[np * 2 + 1][1],
                        sB + (uint32_t)row * 128 + col);
            }
            #pragma unroll
            for (int mi = 0; mi < 4; ++mi)
                #pragma unroll
                for (int ni = 0; ni < 4; ++ni)
                    mma16816(acc[mi][ni], a[mi], b[ni]);
        }
        // no trailing barrier: next iter's WAIT(0)+barrier provides all ordering
    }

    // ---------------- fused dequant epilogue (regs -> gmem) ----------------
    const int g = lane >> 2;
    const int tg = lane & 3;
    #pragma unroll
    for (int mi = 0; mi < 4; ++mi) {
        const int mrow0 = m0 + wm + mi * 16 + g;
        const float rs0 = g_rowsum[mrow0];
        const float rs1 = g_rowsum[mrow0 + 8];
        float* o0 = out + (size_t)mrow0 * NDIM + n0 + wn;
        float* o1 = o0 + (size_t)8 * NDIM;
        #pragma unroll
        for (int ni = 0; ni < 4; ++ni) {
            const int n = n0 + wn + ni * 8 + tg * 2;
            const float2 sc = *reinterpret_cast<const float2*>(scale + n);
            const float2 of = *reinterpret_cast<const float2*>(offs + n);
            const float2 bi = *reinterpret_cast<const float2*>(bias + n);
            const float sox = sc.x * of.x, soy = sc.y * of.y;
            float2 r0v, r1v;
            r0v.x = fmaf(acc[mi][ni][0], sc.x, fmaf(sox, rs0, bi.x));
            r0v.y = fmaf(acc[mi][ni][1], sc.y, fmaf(soy, rs0, bi.y));
            r1v.x = fmaf(acc[mi][ni][2], sc.x, fmaf(sox, rs1, bi.x));
            r1v.y = fmaf(acc[mi][ni][3], sc.y, fmaf(soy, rs1, bi.y));
            *reinterpret_cast<float2*>(o0 + ni * 8 + tg * 2) = r0v;
            *reinterpret_cast<float2*>(o1 + ni * 8 + tg * 2) = r1v;
        }
    }
}

// ---------------------------------------------------------------------------
// Launch
// ---------------------------------------------------------------------------
extern "C" void kernel_launch(void* const* d_in, const int* in_sizes, int n_in,
                              void* d_out, int out_size) {
    const float* x    = (const float*)d_in[0];
    const int*   w    = (const int*)  d_in[1];
    const float* scal = (const float*)d_in[2];
    const float* offs = (const float*)d_in[3];
    const float* bias = (const float*)d_in[4];
    float* out = (float*)d_out;

    cudaFuncSetAttribute(gemm_kernel,
                         cudaFuncAttributeMaxDynamicSharedMemorySize, SMEM_BYTES);

    const unsigned prep_blocks = (unsigned)(MDIM + WCHUNKS);
    prep_kernel<<<prep_blocks, 256>>>(x, w);
    gemm_kernel<<<dim3(MDIM / BM, NDIM / BN), 256, SMEM_BYTES>>>(scal, offs, bias, out);
}